// round 10
// baseline (speedup 1.0000x reference)
#include <cuda_runtime.h>
#include <cstdint>

#define FEAT     128
#define NB_ROWS  50000
#define KNEI     16
#define EMB      128
#define TPB      512
#define GRID     148
#define WTILE    16
#define NWT      (NB_ROWS / WTILE)     // 3125, exact
#define CHUNK    2
#define A_LD     132                   // padded row stride (floats)
#define MTILE    128
#define NTILE    ((NB_ROWS + MTILE - 1) / MTILE)   // 391 (BN apply)

#define A_WARP_FLOATS (WTILE * A_LD)              // 2112
#define SM_W     0                                 // 64KB weight
#define SM_A     65536                             // 16 warps x 8448 B
#define SMEM_BYTES (SM_A + 16 * A_WARP_FLOATS * 4 + 64)   // 200768

typedef unsigned long long ull;

// Scratch (allocation-free rule)
__device__ float g_psum[GRID * EMB];
__device__ float g_psq [GRID * EMB];
__device__ float g_scale[EMB];
__device__ float g_bias [EMB];
__device__ unsigned int g_tile    = 0;
__device__ unsigned int g_arrival = 0;
__device__ unsigned int g_done    = 0;
__device__ unsigned int g_ready   = 0;

// ---- packed f32x2 helpers (Blackwell) ----
__device__ __forceinline__ ull pack2(float x) {
    ull r;
    asm("mov.b64 %0, {%1, %1};" : "=l"(r) : "r"(__float_as_uint(x)));
    return r;
}
__device__ __forceinline__ void fma2(ull& d, ull a, ull b) {
    asm("fma.rn.f32x2 %0, %1, %2, %0;" : "+l"(d) : "l"(a), "l"(b));
}
__device__ __forceinline__ void add2(ull& d, ull a) {
    asm("add.rn.f32x2 %0, %0, %1;" : "+l"(d) : "l"(a));
}
__device__ __forceinline__ void mul2(ull& d, ull a) {
    asm("mul.rn.f32x2 %0, %0, %1;" : "+l"(d) : "l"(a));
}
__device__ __forceinline__ void unpack2(ull v, float& lo, float& hi) {
    unsigned int l, h;
    asm("mov.b64 {%0, %1}, %2;" : "=r"(l), "=r"(h) : "l"(v));
    lo = __uint_as_float(l);
    hi = __uint_as_float(h);
}

// ============================================================================
// Persistent kernel, warp-independent pipeline: each warp owns 16-row
// warp-tiles end-to-end (gather -> GEMM -> epilogue), work from an atomic
// counter. No CTA syncs in the hot loop.
// ============================================================================
__global__ void __launch_bounds__(TPB, 1)
fused_warp(const float* __restrict__ raw,
           const float* __restrict__ W,
           const int* __restrict__ nidx,
           const float* __restrict__ gamma,
           const float* __restrict__ beta,
           float* __restrict__ out)
{
    extern __shared__ char smem[];
    float* s_w = (float*)(smem + SM_W);

    const int tid  = threadIdx.x;
    const int bid  = blockIdx.x;
    const int warp = tid >> 5, lane = tid & 31;
    float* s_a = (float*)(smem + SM_A) + warp * A_WARP_FLOATS;

    // --- load W resident (16384 floats) ---
    {
        const float4* Wv = (const float4*)W;
        float4* sv = (float4*)s_w;
        #pragma unroll
        for (int j = 0; j < 8; j++) sv[tid + j * TPB] = Wv[tid + j * TPB];
    }
    __syncthreads();

    // cross-tile packed column stats: lane's cols (4l,4l+1),(4l+2,4l+3)
    ull cs[2] = {0ULL, 0ULL}, cq[2] = {0ULL, 0ULL};
    const ull inv16 = pack2(1.0f / KNEI);

    const float* bBase = s_w + 4 * lane;

    // ======================= persistent warp loop =======================
    for (;;) {
        int base = 0;
        if (lane == 0) base = (int)atomicAdd(&g_tile, 1u) * CHUNK;
        base = __shfl_sync(0xffffffffu, base, 0);
        if (base >= NWT) break;
        const int lim = (base + CHUNK < NWT) ? base + CHUNK : NWT;

        for (int wt = base; wt < lim; wt++) {
            const int rowBase = wt * WTILE;

            __syncwarp();   // prior GEMM reads of s_a complete
            // --- gather + mean: 8 row-pairs; lane covers cols 4l..4l+3 ---
            #pragma unroll
            for (int rp = 0; rp < 8; rp++) {
                const int r0 = 2 * rp;
                // lanes 0-15: row r0's 16 ids; lanes 16-31: row r0+1's
                const int my =
                    nidx[(rowBase + r0 + (lane >> 4)) * KNEI + (lane & 15)];
                ull a00 = 0ULL, a01 = 0ULL, a10 = 0ULL, a11 = 0ULL;
                #pragma unroll
                for (int k = 0; k < KNEI; k++) {
                    const int id0 = __shfl_sync(0xffffffffu, my, k);
                    const int id1 = __shfl_sync(0xffffffffu, my, 16 + k);
                    const ulonglong2 v0 =
                        ((const ulonglong2*)(raw + (long long)id0 * FEAT))[lane];
                    const ulonglong2 v1 =
                        ((const ulonglong2*)(raw + (long long)id1 * FEAT))[lane];
                    add2(a00, v0.x); add2(a01, v0.y);
                    add2(a10, v1.x); add2(a11, v1.y);
                }
                mul2(a00, inv16); mul2(a01, inv16);
                mul2(a10, inv16); mul2(a11, inv16);
                ulonglong2 st0; st0.x = a00; st0.y = a01;
                ulonglong2 st1; st1.x = a10; st1.y = a11;
                *(ulonglong2*)(s_a + r0 * A_LD + 4 * lane)       = st0;
                *(ulonglong2*)(s_a + (r0 + 1) * A_LD + 4 * lane) = st1;
            }
            __syncwarp();   // gather stores visible to all lanes

            // --- GEMM: lane computes 16 rows x 4 cols (cols 4l..4l+3) ---
            ull acc[WTILE][2];
            #pragma unroll
            for (int r = 0; r < WTILE; r++) { acc[r][0] = 0ULL; acc[r][1] = 0ULL; }

            #pragma unroll 2
            for (int k = 0; k < FEAT; k += 2) {
                const ulonglong2 b0 = *(const ulonglong2*)(bBase + k * EMB);
                const ulonglong2 b1 = *(const ulonglong2*)(bBase + (k + 1) * EMB);
                #pragma unroll
                for (int r = 0; r < WTILE; r++) {
                    const float2 a = *(const float2*)(s_a + r * A_LD + k);
                    const ull a0 = pack2(a.x);
                    const ull a1 = pack2(a.y);
                    fma2(acc[r][0], a0, b0.x);
                    fma2(acc[r][1], a0, b0.y);
                    fma2(acc[r][0], a1, b1.x);
                    fma2(acc[r][1], a1, b1.y);
                }
            }

            // --- epilogue: write pre-BN x + packed column stats ---
            #pragma unroll
            for (int r = 0; r < WTILE; r++) {
                const int rg = rowBase + r;        // always < NB_ROWS
                ulonglong2 v; v.x = acc[r][0]; v.y = acc[r][1];
                *(ulonglong2*)(out + (long long)rg * EMB + 4 * lane) = v;
                add2(cs[0], acc[r][0]); fma2(cq[0], acc[r][0], acc[r][0]);
                add2(cs[1], acc[r][1]); fma2(cq[1], acc[r][1], acc[r][1]);
            }
        }
    }

    // ====================== CTA-level stats reduce ======================
    __syncthreads();           // all warps done; reuse A region
    float* s_sum = (float*)(smem + SM_A);           // [16][128]
    float* s_sq  = (float*)(smem + SM_A) + 2048;    // [16][128]
    {
        float s0, s1, q0, q1;
        unpack2(cs[0], s0, s1); unpack2(cq[0], q0, q1);
        s_sum[warp * 128 + 4 * lane]     = s0;
        s_sum[warp * 128 + 4 * lane + 1] = s1;
        s_sq [warp * 128 + 4 * lane]     = q0;
        s_sq [warp * 128 + 4 * lane + 1] = q1;
        unpack2(cs[1], s0, s1); unpack2(cq[1], q0, q1);
        s_sum[warp * 128 + 4 * lane + 2] = s0;
        s_sum[warp * 128 + 4 * lane + 3] = s1;
        s_sq [warp * 128 + 4 * lane + 2] = q0;
        s_sq [warp * 128 + 4 * lane + 3] = q1;
    }
    __syncthreads();
    if (tid < 128) {
        float s = 0.f, q = 0.f;
        #pragma unroll
        for (int w = 0; w < 16; w++) {
            s += s_sum[w * 128 + tid];
            q += s_sq [w * 128 + tid];
        }
        g_psum[bid * 128 + tid] = s;
        g_psq [bid * 128 + tid] = q;
    }

    // ========================== grid barrier ==========================
    __threadfence();
    __shared__ unsigned int sh_last;
    if (tid == 0)
        sh_last = (atomicAdd(&g_arrival, 1u) == (unsigned)(GRID - 1)) ? 1u : 0u;
    __syncthreads();

    if (sh_last) {
        if (tid < 256) {
            const int c = tid & 127, pp = tid >> 7;    // 2-way split
            float s = 0.f, q = 0.f;
            for (int b = pp; b < GRID; b += 2) {
                s += g_psum[b * 128 + c];
                q += g_psq [b * 128 + c];
            }
            s_sum[pp * 128 + c] = s;
            s_sq [pp * 128 + c] = q;
        }
        __syncthreads();
        if (tid < 128) {
            const float sum = s_sum[tid] + s_sum[128 + tid];
            const float sqq = s_sq [tid] + s_sq [128 + tid];
            const float invN = 1.0f / (float)NB_ROWS;
            const float mean = sum * invN;
            const float var  = sqq * invN - mean * mean;
            const float sc   = gamma[tid] * rsqrtf(var + 1e-5f);
            g_scale[tid] = sc;
            g_bias [tid] = beta[tid] - mean * sc;
        }
        __syncthreads();
        __threadfence();
        if (tid == 0) atomicExch(&g_ready, 1u);
    } else {
        if (tid == 0) {
            unsigned int r;
            do {
                asm volatile("ld.acquire.gpu.b32 %0, [%1];"
                             : "=r"(r) : "l"(&g_ready));
                if (!r) __nanosleep(64);
            } while (!r);
        }
        __syncthreads();
    }

    // ---- BN apply + LeakyReLU (static tile assignment) ----
    __syncthreads();
    if (tid < 128) {
        s_w[tid]       = g_scale[tid];
        s_w[128 + tid] = g_bias[tid];
    }
    __syncthreads();

    for (int tt = bid; tt < NTILE; tt += GRID) {
        const int rowBase = tt * MTILE;
        float4* o4 = (float4*)(out + (long long)rowBase * EMB);
        #pragma unroll
        for (int j = 0; j < 8; j++) {
            const int i = tid + j * TPB;               // 0..4095 float4s
            const int row = i >> 5;
            if (rowBase + row < NB_ROWS) {
                const int c4 = i & 31;
                float4 v = o4[i];
                const float4 sc = ((const float4*)s_w)[c4];
                const float4 bs = ((const float4*)(s_w + 128))[c4];
                float x;
                x = v.x * sc.x + bs.x; v.x = (x >= 0.f) ? x : 0.01f * x;
                x = v.y * sc.y + bs.y; v.y = (x >= 0.f) ? x : 0.01f * x;
                x = v.z * sc.z + bs.z; v.z = (x >= 0.f) ? x : 0.01f * x;
                x = v.w * sc.w + bs.w; v.w = (x >= 0.f) ? x : 0.01f * x;
                o4[i] = v;
            }
        }
    }

    // ---- exit: last CTA resets counters for graph replay ----
    __threadfence();
    __syncthreads();
    if (tid == 0) {
        if (atomicAdd(&g_done, 1u) == (unsigned)(GRID - 1)) {
            g_tile    = 0;
            g_arrival = 0;
            g_done    = 0;
            g_ready   = 0;
            __threadfence();
        }
    }
}

// ============================================================================
extern "C" void kernel_launch(void* const* d_in, const int* in_sizes, int n_in,
                              void* d_out, int out_size)
{
    const float* raw   = (const float*)d_in[0];
    const float* W     = (const float*)d_in[1];
    const float* gamma = (const float*)d_in[2];
    const float* beta  = (const float*)d_in[3];
    const int*   nidx  = (const int*)d_in[4];
    float* out = (float*)d_out;

    cudaFuncSetAttribute(fused_warp,
                         cudaFuncAttributeMaxDynamicSharedMemorySize,
                         SMEM_BYTES);

    fused_warp<<<GRID, TPB, SMEM_BYTES>>>(raw, W, nidx, gamma, beta, out);
}

// round 11
// speedup vs baseline: 1.4555x; 1.4555x over previous
#include <cuda_runtime.h>
#include <cstdint>

#define FEAT     128
#define NB_ROWS  50000
#define KNEI     16
#define EMB      128
#define TPB      512
#define GRID     148
#define STRIP    8
#define NSTRIP   (NB_ROWS / STRIP)      // 6250, exact
#define MTILE    128
#define NTILE    ((NB_ROWS + MTILE - 1) / MTILE)   // 391 (BN apply)

#define SM_W     0                       // 64KB weight
#define SM_A     65536                   // 16 warps x 2 bufs x 8x128 f32
#define SMEM_BYTES (65536 + 16 * 8192 + 64)        // 196672

typedef unsigned long long ull;

// Scratch (allocation-free rule)
__device__ float g_psum[GRID * EMB];
__device__ float g_psq [GRID * EMB];
__device__ float g_scale[EMB];
__device__ float g_bias [EMB];
__device__ unsigned int g_tile    = 0;
__device__ unsigned int g_btile   = 0;
__device__ unsigned int g_arrival = 0;
__device__ unsigned int g_done    = 0;
__device__ unsigned int g_ready   = 0;

// ---- packed f32x2 helpers (Blackwell) ----
__device__ __forceinline__ ull pack2(float x) {
    ull r;
    asm("mov.b64 %0, {%1, %1};" : "=l"(r) : "r"(__float_as_uint(x)));
    return r;
}
__device__ __forceinline__ void fma2(ull& d, ull a, ull b) {
    asm("fma.rn.f32x2 %0, %1, %2, %0;" : "+l"(d) : "l"(a), "l"(b));
}
__device__ __forceinline__ void add2(ull& d, ull a) {
    asm("add.rn.f32x2 %0, %0, %1;" : "+l"(d) : "l"(a));
}
__device__ __forceinline__ void mul2(ull& d, ull a) {
    asm("mul.rn.f32x2 %0, %0, %1;" : "+l"(d) : "l"(a));
}
__device__ __forceinline__ void unpack2(ull v, float& lo, float& hi) {
    unsigned int l, h;
    asm("mov.b64 {%0, %1}, %2;" : "=r"(l), "=r"(h) : "l"(v));
    lo = __uint_as_float(l);
    hi = __uint_as_float(h);
}

__device__ __forceinline__ int fetch_strip() {
    int s = 0;
    if ((threadIdx.x & 31) == 0) s = (int)atomicAdd(&g_tile, 1u);
    return __shfl_sync(0xffffffffu, s, 0);
}

// Gather+mean one row-pair (rows 2rp, 2rp+1) of strip s into bufN.
// Lanes 0-15 carry row0's 16 neighbor ids, lanes 16-31 row1's.
__device__ __forceinline__ void gather_pair(const float* __restrict__ raw,
                                            const int* __restrict__ nidx,
                                            int s, int rp, float* bufN,
                                            int lane, ull inv16) {
    const int r0 = 2 * rp;
    const int my = nidx[(s * STRIP + r0 + (lane >> 4)) * KNEI + (lane & 15)];
    ull a00 = 0ULL, a01 = 0ULL, a10 = 0ULL, a11 = 0ULL;
    #pragma unroll
    for (int k = 0; k < KNEI; k++) {
        const int id0 = __shfl_sync(0xffffffffu, my, k);
        const int id1 = __shfl_sync(0xffffffffu, my, 16 + k);
        const ulonglong2 v0 =
            ((const ulonglong2*)(raw + (long long)id0 * FEAT))[lane];
        const ulonglong2 v1 =
            ((const ulonglong2*)(raw + (long long)id1 * FEAT))[lane];
        add2(a00, v0.x); add2(a01, v0.y);
        add2(a10, v1.x); add2(a11, v1.y);
    }
    mul2(a00, inv16); mul2(a01, inv16);
    mul2(a10, inv16); mul2(a11, inv16);
    ulonglong2 s0; s0.x = a00; s0.y = a01;
    ulonglong2 s1; s1.x = a10; s1.y = a11;
    *(ulonglong2*)(bufN + r0 * FEAT + 4 * lane)       = s0;
    *(ulonglong2*)(bufN + (r0 + 1) * FEAT + 4 * lane) = s1;
}

// ============================================================================
// Persistent kernel: warp-private 8-row strips, dynamic work stealing,
// double-buffered A, gather-of-next-strip interleaved into the GEMM k-loop.
// No CTA syncs in the hot loop.
// ============================================================================
__global__ void __launch_bounds__(TPB, 1)
fused_sp(const float* __restrict__ raw,
         const float* __restrict__ W,
         const int* __restrict__ nidx,
         const float* __restrict__ gamma,
         const float* __restrict__ beta,
         float* __restrict__ out)
{
    extern __shared__ char smem[];
    float* s_w = (float*)(smem + SM_W);

    const int tid  = threadIdx.x;
    const int bid  = blockIdx.x;
    const int warp = tid >> 5, lane = tid & 31;
    float* myA = (float*)(smem + SM_A) + warp * (2 * STRIP * FEAT);

    // --- load W resident (16384 floats) ---
    {
        const float4* Wv = (const float4*)W;
        float4* sv = (float4*)s_w;
        #pragma unroll
        for (int j = 0; j < 8; j++) sv[tid + j * TPB] = Wv[tid + j * TPB];
    }
    __syncthreads();

    const ull inv16 = pack2(1.0f / KNEI);
    const float* bBase = s_w + 4 * lane;

    // cross-strip packed column stats: lane's cols (4l,4l+1),(4l+2,4l+3)
    ull cs[2] = {0ULL, 0ULL}, cq[2] = {0ULL, 0ULL};

    // --- prologue: first strip gathered standalone ---
    int sc = fetch_strip();
    int p = 0;
    if (sc < NSTRIP) {
        #pragma unroll
        for (int rp = 0; rp < 4; rp++)
            gather_pair(raw, nidx, sc, rp, myA, lane, inv16);
    }
    int sn = fetch_strip();

    // ======================= persistent warp loop =======================
    while (sc < NSTRIP) {
        __syncwarp();      // gather stores of buf[p] visible; buf[p^1] free
        float* sA  = myA + p * (STRIP * FEAT);
        float* sAn = myA + (p ^ 1) * (STRIP * FEAT);
        const bool hn = (sn < NSTRIP);

        ull acc[STRIP][2];
        #pragma unroll
        for (int r = 0; r < STRIP; r++) { acc[r][0] = 0ULL; acc[r][1] = 0ULL; }

        #pragma unroll
        for (int c = 0; c < 4; c++) {
            // gather one row-pair of next strip per 32-k chunk
            if (hn) gather_pair(raw, nidx, sn, c, sAn, lane, inv16);

            const int k0 = c * 32;
            #pragma unroll
            for (int kq = 0; kq < 32; kq += 4) {
                const int k = k0 + kq;
                const ulonglong2 b0 = *(const ulonglong2*)(bBase + k * EMB);
                const ulonglong2 b1 = *(const ulonglong2*)(bBase + (k + 1) * EMB);
                const ulonglong2 b2 = *(const ulonglong2*)(bBase + (k + 2) * EMB);
                const ulonglong2 b3 = *(const ulonglong2*)(bBase + (k + 3) * EMB);
                #pragma unroll
                for (int r = 0; r < STRIP; r++) {
                    const float4 a = *(const float4*)(sA + r * FEAT + k);
                    const ull ax = pack2(a.x), ay = pack2(a.y);
                    const ull az = pack2(a.z), aw = pack2(a.w);
                    fma2(acc[r][0], ax, b0.x); fma2(acc[r][1], ax, b0.y);
                    fma2(acc[r][0], ay, b1.x); fma2(acc[r][1], ay, b1.y);
                    fma2(acc[r][0], az, b2.x); fma2(acc[r][1], az, b2.y);
                    fma2(acc[r][0], aw, b3.x); fma2(acc[r][1], aw, b3.y);
                }
            }
        }

        // --- epilogue: write pre-BN x + packed column stats ---
        const int rowBase = sc * STRIP;     // all rows valid (50000 = 6250*8)
        #pragma unroll
        for (int r = 0; r < STRIP; r++) {
            ulonglong2 v; v.x = acc[r][0]; v.y = acc[r][1];
            *(ulonglong2*)(out + (long long)(rowBase + r) * EMB + 4 * lane) = v;
            add2(cs[0], acc[r][0]); fma2(cq[0], acc[r][0], acc[r][0]);
            add2(cs[1], acc[r][1]); fma2(cq[1], acc[r][1], acc[r][1]);
        }

        sc = sn;
        p ^= 1;
        sn = fetch_strip();
    }

    // ====================== CTA-level stats reduce ======================
    __syncthreads();           // all warps done; reuse A region
    float* s_sum = (float*)(smem + SM_A);           // [16][128]
    float* s_sq  = (float*)(smem + SM_A) + 2048;    // [16][128]
    {
        float s0, s1, q0, q1;
        unpack2(cs[0], s0, s1); unpack2(cq[0], q0, q1);
        s_sum[warp * 128 + 4 * lane]     = s0;
        s_sum[warp * 128 + 4 * lane + 1] = s1;
        s_sq [warp * 128 + 4 * lane]     = q0;
        s_sq [warp * 128 + 4 * lane + 1] = q1;
        unpack2(cs[1], s0, s1); unpack2(cq[1], q0, q1);
        s_sum[warp * 128 + 4 * lane + 2] = s0;
        s_sum[warp * 128 + 4 * lane + 3] = s1;
        s_sq [warp * 128 + 4 * lane + 2] = q0;
        s_sq [warp * 128 + 4 * lane + 3] = q1;
    }
    __syncthreads();
    if (tid < 128) {
        float s = 0.f, q = 0.f;
        #pragma unroll
        for (int w = 0; w < 16; w++) {
            s += s_sum[w * 128 + tid];
            q += s_sq [w * 128 + tid];
        }
        g_psum[bid * 128 + tid] = s;
        g_psq [bid * 128 + tid] = q;
    }

    // ========================== grid barrier ==========================
    __threadfence();
    __shared__ unsigned int sh_last;
    if (tid == 0)
        sh_last = (atomicAdd(&g_arrival, 1u) == (unsigned)(GRID - 1)) ? 1u : 0u;
    __syncthreads();

    if (sh_last) {
        if (tid < 256) {
            const int c = tid & 127, pp = tid >> 7;    // 2-way split
            float s = 0.f, q = 0.f;
            for (int b = pp; b < GRID; b += 2) {
                s += g_psum[b * 128 + c];
                q += g_psq [b * 128 + c];
            }
            s_sum[pp * 128 + c] = s;
            s_sq [pp * 128 + c] = q;
        }
        __syncthreads();
        if (tid < 128) {
            const float sum = s_sum[tid] + s_sum[128 + tid];
            const float sqq = s_sq [tid] + s_sq [128 + tid];
            const float invN = 1.0f / (float)NB_ROWS;
            const float mean = sum * invN;
            const float var  = sqq * invN - mean * mean;
            const float sc2  = gamma[tid] * rsqrtf(var + 1e-5f);
            g_scale[tid] = sc2;
            g_bias [tid] = beta[tid] - mean * sc2;
        }
        __syncthreads();
        __threadfence();
        if (tid == 0) atomicExch(&g_ready, 1u);
    } else {
        if (tid == 0) {
            unsigned int r;
            do {
                asm volatile("ld.acquire.gpu.b32 %0, [%1];"
                             : "=r"(r) : "l"(&g_ready));
                if (!r) __nanosleep(64);
            } while (!r);
        }
        __syncthreads();
    }

    // ---- BN apply + LeakyReLU (dynamic 128-row tiles) ----
    __syncthreads();
    if (tid < 128) {
        s_w[tid]       = g_scale[tid];
        s_w[128 + tid] = g_bias[tid];
    }
    __shared__ unsigned int sh_bt;
    for (;;) {
        __syncthreads();
        if (tid == 0) sh_bt = atomicAdd(&g_btile, 1u);
        __syncthreads();
        const int tt = (int)sh_bt;
        if (tt >= NTILE) break;

        const int rowBase = tt * MTILE;
        float4* o4 = (float4*)(out + (long long)rowBase * EMB);
        #pragma unroll
        for (int j = 0; j < 8; j++) {
            const int i = tid + j * TPB;               // 0..4095 float4s
            const int row = i >> 5;
            if (rowBase + row < NB_ROWS) {
                const int c4 = i & 31;
                float4 v = o4[i];
                const float4 sc3 = ((const float4*)s_w)[c4];
                const float4 bs  = ((const float4*)(s_w + 128))[c4];
                float x;
                x = v.x * sc3.x + bs.x; v.x = (x >= 0.f) ? x : 0.01f * x;
                x = v.y * sc3.y + bs.y; v.y = (x >= 0.f) ? x : 0.01f * x;
                x = v.z * sc3.z + bs.z; v.z = (x >= 0.f) ? x : 0.01f * x;
                x = v.w * sc3.w + bs.w; v.w = (x >= 0.f) ? x : 0.01f * x;
                o4[i] = v;
            }
        }
    }

    // ---- exit: last CTA resets counters for graph replay ----
    __threadfence();
    __syncthreads();
    if (tid == 0) {
        if (atomicAdd(&g_done, 1u) == (unsigned)(GRID - 1)) {
            g_tile    = 0;
            g_btile   = 0;
            g_arrival = 0;
            g_done    = 0;
            g_ready   = 0;
            __threadfence();
        }
    }
}

// ============================================================================
extern "C" void kernel_launch(void* const* d_in, const int* in_sizes, int n_in,
                              void* d_out, int out_size)
{
    const float* raw   = (const float*)d_in[0];
    const float* W     = (const float*)d_in[1];
    const float* gamma = (const float*)d_in[2];
    const float* beta  = (const float*)d_in[3];
    const int*   nidx  = (const int*)d_in[4];
    float* out = (float*)d_out;

    cudaFuncSetAttribute(fused_sp,
                         cudaFuncAttributeMaxDynamicSharedMemorySize,
                         SMEM_BYTES);

    fused_sp<<<GRID, TPB, SMEM_BYTES>>>(raw, W, nidx, gamma, beta, out);
}